// round 10
// baseline (speedup 1.0000x reference)
#include <cuda_runtime.h>
#include <cstdint>

typedef uint32_t u32;

// Per-problem smem regions (bytes), bf16 [64x64], rows 128B, XOR-swizzled granules.
#define R_QH 0
#define R_QL 8192
#define R_KH 16384
#define R_KL 24576
#define R_VH 32768
#define R_VL 40960
#define PROB_STRIDE 49152          // bytes per problem
#define SMEM_BYTES  98304          // 2 problems per CTA
// O staging (f32, stride 68 floats, 17408 B) overlays Q/K after the pre-staging barrier.

__device__ __forceinline__ u32 smem_u32(const void* p) {
    u32 a;
    asm("{ .reg .u64 t; cvta.to.shared.u64 t, %1; cvt.u32.u64 %0, t; }" : "=r"(a) : "l"(p));
    return a;
}
__device__ __forceinline__ u32 pack_h(float f0, float f1) {   // lo=f0, hi=f1
    u32 r;
    asm("cvt.rn.bf16x2.f32 %0, %1, %2;" : "=r"(r) : "f"(f1), "f"(f0));
    return r;
}
__device__ __forceinline__ u32 pack_l(u32 h, float f0, float f1) {
    float r0 = f0 - __uint_as_float(h << 16);
    float r1 = f1 - __uint_as_float(h & 0xffff0000u);
    return pack_h(r0, r1);
}
__device__ __forceinline__ void ldsm4(u32* r, u32 addr) {
    asm volatile("ldmatrix.sync.aligned.m8n8.x4.shared.b16 {%0,%1,%2,%3}, [%4];"
        : "=r"(r[0]), "=r"(r[1]), "=r"(r[2]), "=r"(r[3]) : "r"(addr));
}
__device__ __forceinline__ void ldsm4t(u32* r, u32 addr) {
    asm volatile("ldmatrix.sync.aligned.m8n8.x4.trans.shared.b16 {%0,%1,%2,%3}, [%4];"
        : "=r"(r[0]), "=r"(r[1]), "=r"(r[2]), "=r"(r[3]) : "r"(addr));
}
__device__ __forceinline__ void mma16816(float* c, const u32* a, const u32* b) {
    asm volatile(
        "mma.sync.aligned.m16n8k16.row.col.f32.bf16.bf16.f32 "
        "{%0,%1,%2,%3}, {%4,%5,%6,%7}, {%8,%9}, {%0,%1,%2,%3};"
        : "+f"(c[0]), "+f"(c[1]), "+f"(c[2]), "+f"(c[3])
        : "r"(a[0]), "r"(a[1]), "r"(a[2]), "r"(a[3]), "r"(b[0]), "r"(b[1]));
}

__global__ void __launch_bounds__(128, 2)
attn64_wmma2(const float* __restrict__ qg_, const float* __restrict__ kg_,
             const float* __restrict__ vg_, const int* __restrict__ mg_,
             float* __restrict__ og_)
{
    extern __shared__ char smem[];
    const u32 sbase = smem_u32(smem);
    const int tid  = threadIdx.x;
    const int lane = tid & 31;
    const int w    = tid >> 5;

    const int pg0 = blockIdx.x << 1;             // 2 contiguous problems per CTA
    const float* qg = qg_ + (size_t)pg0 * 4096;  // 8192 floats = both problems
    const float* kg = kg_ + (size_t)pg0 * 4096;
    const float* vg = vg_ + (size_t)pg0 * 4096;
    const int*   mg = mg_ + (size_t)(pg0 >> 9) * 4096;   // same b for pg0, pg0+1
    float*       og = og_ + (size_t)pg0 * 4096;

    // ---- Stage both problems: fp32 -> (hi,lo) bf16, swizzled granule^(row&7) ----
    // 1024 granules total (2 problems x 512), 128 threads -> 8 iterations.
    #pragma unroll
    for (int it = 0; it < 8; it++) {
        int idx = tid + (it << 7);               // 0..1023
        int e = idx << 3;                        // 8 source floats (0..8184)
        int r = idx >> 3;                        // stacked row 0..127
        int h = idx & 7;
        int pr = r >> 6, rr = r & 63;
        int off = pr * PROB_STRIDE + (rr << 7) + ((h ^ (rr & 7)) << 4);
        float4 f0, f1;
        uint4 hq, lq;

        f0 = *reinterpret_cast<const float4*>(qg + e);
        f1 = *reinterpret_cast<const float4*>(qg + e + 4);
        hq.x = pack_h(f0.x, f0.y); hq.y = pack_h(f0.z, f0.w);
        hq.z = pack_h(f1.x, f1.y); hq.w = pack_h(f1.z, f1.w);
        lq.x = pack_l(hq.x, f0.x, f0.y); lq.y = pack_l(hq.y, f0.z, f0.w);
        lq.z = pack_l(hq.z, f1.x, f1.y); lq.w = pack_l(hq.w, f1.z, f1.w);
        *reinterpret_cast<uint4*>(smem + R_QH + off) = hq;
        *reinterpret_cast<uint4*>(smem + R_QL + off) = lq;

        f0 = *reinterpret_cast<const float4*>(kg + e);
        f1 = *reinterpret_cast<const float4*>(kg + e + 4);
        hq.x = pack_h(f0.x, f0.y); hq.y = pack_h(f0.z, f0.w);
        hq.z = pack_h(f1.x, f1.y); hq.w = pack_h(f1.z, f1.w);
        lq.x = pack_l(hq.x, f0.x, f0.y); lq.y = pack_l(hq.y, f0.z, f0.w);
        lq.z = pack_l(hq.z, f1.x, f1.y); lq.w = pack_l(hq.w, f1.z, f1.w);
        *reinterpret_cast<uint4*>(smem + R_KH + off) = hq;
        *reinterpret_cast<uint4*>(smem + R_KL + off) = lq;

        f0 = *reinterpret_cast<const float4*>(vg + e);
        f1 = *reinterpret_cast<const float4*>(vg + e + 4);
        hq.x = pack_h(f0.x, f0.y); hq.y = pack_h(f0.z, f0.w);
        hq.z = pack_h(f1.x, f1.y); hq.w = pack_h(f1.z, f1.w);
        lq.x = pack_l(hq.x, f0.x, f0.y); lq.y = pack_l(hq.y, f0.z, f0.w);
        lq.z = pack_l(hq.z, f1.x, f1.y); lq.w = pack_l(hq.w, f1.z, f1.w);
        *reinterpret_cast<uint4*>(smem + R_VH + off) = hq;
        *reinterpret_cast<uint4*>(smem + R_VL + off) = lq;
    }
    __syncthreads();

    // ---- Warp assignment: problem p = w>>1; warp-in-problem covers 32 rows ----
    const int p  = w >> 1;
    const int ww = w & 1;                        // rows 32*ww .. 32*ww+31 (2 tiles)
    const u32 sp = sbase + (u32)p * PROB_STRIDE;

    const int sw      = lane & 7;
    const int arow_l  = (lane & 7) + (((lane >> 3) & 1) << 3);
    const int a_ga    = lane >> 4;               // A order: (r,g)(r8,g)(r,g1)(r8,g1)
    const int tau     = lane >> 3;
    const int kb_radd = ((tau >> 1) << 3) + (lane & 7);  // K order: (r,g)(r,g1)(r8,g)(r8,g1)
    const int kb_ga   = tau & 1;
    const int vb_radd = ((tau & 1) << 3) + (lane & 7);   // V order: (k,g)(k8,g)(k,g1)(k8,g1)
    const int vb_ga   = tau >> 1;

    // ---- S = Q K^T : 2 row-tiles x 8 n-frags, 3-pass bf16 split ----
    float accS[2][8][4];
    #pragma unroll
    for (int t = 0; t < 2; t++)
        #pragma unroll
        for (int n = 0; n < 8; n++)
            #pragma unroll
            for (int i = 0; i < 4; i++) accS[t][n][i] = 0.0f;

    #pragma unroll
    for (int kc = 0; kc < 4; kc++) {
        int ag = (kc << 1) + a_ga;
        u32 qh[2][4], ql[2][4];
        #pragma unroll
        for (int t = 0; t < 2; t++) {
            int arow = (ww << 5) + (t << 4) + arow_l;    // arow&7 == sw
            u32 ao = sp + (u32)(arow << 7) + (u32)((ag ^ sw) << 4);
            ldsm4(qh[t], ao + R_QH);
            ldsm4(ql[t], ao + R_QL);
        }
        int kg_ = (kc << 1) + kb_ga;
        u32 kh[16], kl[16];
        #pragma unroll
        for (int np = 0; np < 4; np++) {
            u32 roff = (u32)(((np << 4) + kb_radd) << 7) + (u32)((kg_ ^ sw) << 4);
            ldsm4(&kh[np << 2], sp + R_KH + roff);
            ldsm4(&kl[np << 2], sp + R_KL + roff);
        }
        #pragma unroll
        for (int t = 0; t < 2; t++)
            #pragma unroll
            for (int n = 0; n < 8; n++) {
                mma16816(accS[t][n], qh[t], &kh[n << 1]);
                mma16816(accS[t][n], qh[t], &kl[n << 1]);
                mma16816(accS[t][n], ql[t], &kh[n << 1]);
            }
    }

    // ---- Softmax per row-tile, fully in registers; pack P A-frags ----
    const int cb = (lane & 3) << 1;
    u32 ph[2][4][4], pl[2][4][4];
    #pragma unroll
    for (int t = 0; t < 2; t++) {
        const int r0 = (ww << 5) + (t << 4) + (lane >> 2);
        const int r1 = r0 + 8;
        int2 m0[8], m1[8];
        #pragma unroll
        for (int n = 0; n < 8; n++) {
            m0[n] = *reinterpret_cast<const int2*>(mg + (r0 << 6) + (n << 3) + cb);
            m1[n] = *reinterpret_cast<const int2*>(mg + (r1 << 6) + (n << 3) + cb);
        }
        float p0[16], p1[16];
        #pragma unroll
        for (int n = 0; n < 8; n++) {
            p0[2*n]   = (m0[n].x == 0) ? -32768.0f : accS[t][n][0] * 0.125f;
            p0[2*n+1] = (m0[n].y == 0) ? -32768.0f : accS[t][n][1] * 0.125f;
            p1[2*n]   = (m1[n].x == 0) ? -32768.0f : accS[t][n][2] * 0.125f;
            p1[2*n+1] = (m1[n].y == 0) ? -32768.0f : accS[t][n][3] * 0.125f;
        }
        float mx0 = p0[0], mx1 = p1[0];
        #pragma unroll
        for (int j = 1; j < 16; j++) { mx0 = fmaxf(mx0, p0[j]); mx1 = fmaxf(mx1, p1[j]); }
        mx0 = fmaxf(mx0, __shfl_xor_sync(0xffffffffu, mx0, 1));
        mx0 = fmaxf(mx0, __shfl_xor_sync(0xffffffffu, mx0, 2));
        mx1 = fmaxf(mx1, __shfl_xor_sync(0xffffffffu, mx1, 1));
        mx1 = fmaxf(mx1, __shfl_xor_sync(0xffffffffu, mx1, 2));
        float s0 = 0.0f, s1 = 0.0f;
        #pragma unroll
        for (int j = 0; j < 16; j++) {
            p0[j] = __expf(p0[j] - mx0); s0 += p0[j];
            p1[j] = __expf(p1[j] - mx1); s1 += p1[j];
        }
        s0 += __shfl_xor_sync(0xffffffffu, s0, 1);
        s0 += __shfl_xor_sync(0xffffffffu, s0, 2);
        s1 += __shfl_xor_sync(0xffffffffu, s1, 1);
        s1 += __shfl_xor_sync(0xffffffffu, s1, 2);
        const float i0 = 1.0f / s0, i1 = 1.0f / s1;
        #pragma unroll
        for (int j = 0; j < 16; j++) { p0[j] *= i0; p1[j] *= i1; }
        #pragma unroll
        for (int kc = 0; kc < 4; kc++) {
            ph[t][kc][0] = pack_h(p0[4*kc],   p0[4*kc+1]);
            ph[t][kc][1] = pack_h(p1[4*kc],   p1[4*kc+1]);
            ph[t][kc][2] = pack_h(p0[4*kc+2], p0[4*kc+3]);
            ph[t][kc][3] = pack_h(p1[4*kc+2], p1[4*kc+3]);
            pl[t][kc][0] = pack_l(ph[t][kc][0], p0[4*kc],   p0[4*kc+1]);
            pl[t][kc][1] = pack_l(ph[t][kc][1], p1[4*kc],   p1[4*kc+1]);
            pl[t][kc][2] = pack_l(ph[t][kc][2], p0[4*kc+2], p0[4*kc+3]);
            pl[t][kc][3] = pack_l(ph[t][kc][3], p1[4*kc+2], p1[4*kc+3]);
        }
    }

    // ---- O = P V : V B-frags shared across both row-tiles ----
    float oacc[2][8][4];
    #pragma unroll
    for (int t = 0; t < 2; t++)
        #pragma unroll
        for (int n = 0; n < 8; n++)
            #pragma unroll
            for (int i = 0; i < 4; i++) oacc[t][n][i] = 0.0f;

    #pragma unroll
    for (int kc = 0; kc < 4; kc++) {
        u32 vh[16], vl[16];
        #pragma unroll
        for (int np = 0; np < 4; np++) {
            int vgr = (np << 1) + vb_ga;
            u32 roff = (u32)(((kc << 4) + vb_radd) << 7) + (u32)((vgr ^ sw) << 4);
            ldsm4t(&vh[np << 2], sp + R_VH + roff);
            ldsm4t(&vl[np << 2], sp + R_VL + roff);
        }
        #pragma unroll
        for (int t = 0; t < 2; t++)
            #pragma unroll
            for (int n = 0; n < 8; n++) {
                mma16816(oacc[t][n], ph[t][kc], &vh[n << 1]);
                mma16816(oacc[t][n], ph[t][kc], &vl[n << 1]);
                mma16816(oacc[t][n], pl[t][kc], &vh[n << 1]);
            }
    }

    // ---- Barrier: no warp may still be reading Q/K before staging overlay ----
    __syncthreads();

    // ---- Stage O (f32, stride 68) over dead Q/K region; coalesced stores ----
    float* stag = reinterpret_cast<float*>(smem) + p * (PROB_STRIDE / 4);
    #pragma unroll
    for (int t = 0; t < 2; t++) {
        const int r0 = (ww << 5) + (t << 4) + (lane >> 2);
        const int r1 = r0 + 8;
        #pragma unroll
        for (int n = 0; n < 8; n++) {
            *reinterpret_cast<float2*>(stag + r0 * 68 + (n << 3) + cb) =
                make_float2(oacc[t][n][0], oacc[t][n][1]);
            *reinterpret_cast<float2*>(stag + r1 * 68 + (n << 3) + cb) =
                make_float2(oacc[t][n][2], oacc[t][n][3]);
        }
    }
    __syncthreads();
    float* smf = reinterpret_cast<float*>(smem);
    #pragma unroll
    for (int it = 0; it < 16; it++) {
        int e = (tid + (it << 7)) << 2;          // 0..8188
        int r = e >> 6, c = e & 63;
        int pr = r >> 6, rr = r & 63;
        *reinterpret_cast<float4*>(og + e) =
            *reinterpret_cast<const float4*>(smf + pr * (PROB_STRIDE / 4) + rr * 68 + c);
    }
}

extern "C" void kernel_launch(void* const* d_in, const int* in_sizes, int n_in,
                              void* d_out, int out_size) {
    const float* q    = (const float*)d_in[0];
    const float* k    = (const float*)d_in[1];
    const float* v    = (const float*)d_in[2];
    const int*   mask = (const int*)  d_in[3];
    float*       out  = (float*)d_out;

    cudaFuncSetAttribute(attn64_wmma2,
                         cudaFuncAttributeMaxDynamicSharedMemorySize, SMEM_BYTES);
    attn64_wmma2<<<4096, 128, SMEM_BYTES>>>(q, k, v, mask, out);
}